// round 8
// baseline (speedup 1.0000x reference)
#include <cuda_runtime.h>
#include <cuda_bf16.h>
#include <cstdint>
#include <math.h>

// Problem constants
#define BATCH 8
#define CH    192
#define HH    128
#define WW    128
#define HEADS 6
#define HD    32
#define WIN   8
#define NTOK  64
#define NWIN  2048
#define TOK   131072
#define HID   768
#define SHIFT 4

// ---------------- device scratch ----------------
__device__ __align__(256) float g_xb [TOK * CH];   // GN output NHWC fp32 (residual & shortcut)
__device__ __align__(256) float g_xb2[TOK * CH];   // xb + attn branch NHWC fp32
__device__ __align__(256) __nv_bfloat16 g_hw_bf [TOK * CH];
// qkv in head-major layout: [win][head][mat(q,k,v)][64 tok][32 dim]
__device__ __align__(256) __nv_bfloat16 g_qkv_bf[(size_t)TOK * 3 * CH];
__device__ __align__(256) __nv_bfloat16 g_attn_bf[TOK * CH];
__device__ __align__(256) __nv_bfloat16 g_h2_bf [TOK * CH];
__device__ __align__(256) __nv_bfloat16 g_hid_bf[(size_t)TOK * HID];
__device__ __align__(256) __nv_bfloat16 g_wqkv[3 * CH * CH];   // [576,192] (N,K)
__device__ __align__(256) __nv_bfloat16 g_wproj[CH * CH];      // [192,192]
__device__ __align__(256) __nv_bfloat16 g_wfc1[HID * CH];      // [768,192]
__device__ __align__(256) __nv_bfloat16 g_wfc2[CH * HID];      // [192,768]
__device__ float g_part[BATCH * 128 * 2];
__device__ float g_stats[BATCH * 2];

// ---------------- helpers ----------------
__device__ __forceinline__ uint32_t s2u(const void* p) {
    uint32_t a;
    asm("{ .reg .u64 t; cvta.to.shared.u64 t, %1; cvt.u32.u64 %0, t; }" : "=r"(a) : "l"(p));
    return a;
}
__device__ __forceinline__ uint32_t sw128(uint32_t o) { return o ^ ((o >> 3) & 0x70); }

__device__ __forceinline__ void cp16(uint32_t saddr, const void* gptr) {
    asm volatile("cp.async.cg.shared.global [%0], [%1], 16;" :: "r"(saddr), "l"(gptr) : "memory");
}
__device__ __forceinline__ void cp_commit() {
    asm volatile("cp.async.commit_group;" ::: "memory");
}
__device__ __forceinline__ void cp_wait2() {
    asm volatile("cp.async.wait_group 2;" ::: "memory");
}
__device__ __forceinline__ void ldsm4(uint32_t& r0, uint32_t& r1, uint32_t& r2, uint32_t& r3,
                                      uint32_t a) {
    asm volatile("ldmatrix.sync.aligned.m8n8.x4.shared.b16 {%0,%1,%2,%3}, [%4];"
                 : "=r"(r0), "=r"(r1), "=r"(r2), "=r"(r3) : "r"(a));
}
__device__ __forceinline__ void ldsm4t(uint32_t& r0, uint32_t& r1, uint32_t& r2, uint32_t& r3,
                                       uint32_t a) {
    asm volatile("ldmatrix.sync.aligned.m8n8.x4.trans.shared.b16 {%0,%1,%2,%3}, [%4];"
                 : "=r"(r0), "=r"(r1), "=r"(r2), "=r"(r3) : "r"(a));
}
__device__ __forceinline__ void mma16816(float* c, const uint32_t* a, const uint32_t* b) {
    asm volatile(
        "mma.sync.aligned.m16n8k16.row.col.f32.bf16.bf16.f32 "
        "{%0,%1,%2,%3}, {%4,%5,%6,%7}, {%8,%9}, {%0,%1,%2,%3};"
        : "+f"(c[0]), "+f"(c[1]), "+f"(c[2]), "+f"(c[3])
        : "r"(a[0]), "r"(a[1]), "r"(a[2]), "r"(a[3]), "r"(b[0]), "r"(b[1]));
}
__device__ __forceinline__ uint32_t packbf(float a, float b) {
    __nv_bfloat162 h = __floats2bfloat162_rn(a, b);
    return *(uint32_t*)&h;
}

// ---------------- GroupNorm two-stage reduction ----------------
__global__ void gn_partial_kernel(const float* __restrict__ x) {
    const int b = blockIdx.x >> 7;
    const int chunk = blockIdx.x & 127;
    const int tid = threadIdx.x;
    const size_t per_sample = (size_t)CH * HH * WW;
    const float* p = x + (size_t)b * per_sample + (size_t)chunk * 24576;
    float s = 0.f, sq = 0.f;
    for (int i = tid; i < 24576; i += 256) { float v = p[i]; s += v; sq += v * v; }
    __shared__ float rs[256], rq[256];
    rs[tid] = s; rq[tid] = sq;
    __syncthreads();
    for (int o = 128; o; o >>= 1) {
        if (tid < o) { rs[tid] += rs[tid + o]; rq[tid] += rq[tid + o]; }
        __syncthreads();
    }
    if (tid == 0) {
        g_part[blockIdx.x * 2 + 0] = rs[0];
        g_part[blockIdx.x * 2 + 1] = rq[0];
    }
}

__global__ void gn_final_kernel() {
    const int b = blockIdx.x;
    const int tid = threadIdx.x;
    __shared__ double ds[128], dq[128];
    ds[tid] = (double)g_part[(b * 128 + tid) * 2 + 0];
    dq[tid] = (double)g_part[(b * 128 + tid) * 2 + 1];
    __syncthreads();
    for (int o = 64; o; o >>= 1) {
        if (tid < o) { ds[tid] += ds[tid + o]; dq[tid] += dq[tid + o]; }
        __syncthreads();
    }
    if (tid == 0) {
        const double n = 3145728.0;
        double mean = ds[0] / n;
        double var = dq[0] / n - mean * mean;
        g_stats[b * 2 + 0] = (float)mean;
        g_stats[b * 2 + 1] = (float)(1.0 / sqrt(var + 1e-5));
    }
}

// ---------------- all weight transposes in one launch ----------------
__global__ void wtrans_all(const float* __restrict__ qkv_w, const float* __restrict__ proj_w,
                           const float* __restrict__ fc1_w, const float* __restrict__ fc2_w) {
    const int b = blockIdx.x;
    const float* W;
    __nv_bfloat16* Wt;
    int K, N, bx, by;
    if (b < 108)      { W = qkv_w;  Wt = g_wqkv;  K = CH;  N = 3 * CH; bx = b % 18;  by = b / 18; }
    else if (b < 144) { int t = b - 108; W = proj_w; Wt = g_wproj; K = CH;  N = CH;  bx = t % 6;  by = t / 6; }
    else if (b < 288) { int t = b - 144; W = fc1_w;  Wt = g_wfc1;  K = CH;  N = HID; bx = t % 24; by = t / 24; }
    else              { int t = b - 288; W = fc2_w;  Wt = g_wfc2;  K = HID; N = CH;  bx = t % 6;  by = t / 6; }
    __shared__ float t[32][33];
    const int k0 = by * 32, n0 = bx * 32;
    const int lx = threadIdx.x & 31, ly = threadIdx.x >> 5;
    for (int r = ly; r < 32; r += 8) t[r][lx] = W[(size_t)(k0 + r) * N + n0 + lx];
    __syncthreads();
    for (int r = ly; r < 32; r += 8)
        Wt[(size_t)(n0 + r) * K + k0 + lx] = __float2bfloat16(t[lx][r]);
}

// ---------------- GN apply + xb store + LN1 + shift + window partition ----------------
__global__ void build_kernel(const float* __restrict__ x,
                             const float* __restrict__ gnw, const float* __restrict__ gnb,
                             const float* __restrict__ ln1w, const float* __restrict__ ln1b) {
    __shared__ float t[CH][33];
    const int bid = blockIdx.x;
    const int xt = bid & 3;
    const int y  = (bid >> 2) & 127;
    const int b  = bid >> 9;
    const int tid = threadIdx.x;
    const float mu = g_stats[b * 2 + 0];
    const float rstd = g_stats[b * 2 + 1];
    const int lx = tid & 31;
    const int c0 = tid >> 5;

    for (int c = c0; c < CH; c += 8) {
        float v = x[((((size_t)b * CH + c) * HH + y) * WW) + xt * 32 + lx];
        t[c][lx] = (v - mu) * rstd * gnw[c] + gnb[c];
    }
    __syncthreads();

    const size_t tokbase = ((size_t)(b * HH + y) * WW) + xt * 32;
    for (int j = 0; j < 32; j++) {
        if (tid < CH) g_xb[(tokbase + j) * CH + tid] = t[tid][j];
    }

    const int warp = tid >> 5, lane = tid & 31;
    for (int j = warp; j < 32; j += 8) {
        float s = 0.f, sq = 0.f;
#pragma unroll
        for (int k = 0; k < 6; k++) {
            float v = t[lane + k * 32][j];
            s += v; sq += v * v;
        }
#pragma unroll
        for (int o = 16; o; o >>= 1) {
            s  += __shfl_xor_sync(0xffffffffu, s, o);
            sq += __shfl_xor_sync(0xffffffffu, sq, o);
        }
        float mean = s * (1.f / CH);
        float var = sq * (1.f / CH) - mean * mean;
        float r = rsqrtf(var + 1e-5f);
        const int xx = xt * 32 + j;
        const int ys = (y - SHIFT) & 127;
        const int xs = (xx - SHIFT) & 127;
        const size_t dst = ((size_t)(((b * 16 + (ys >> 3)) * 16 + (xs >> 3)) * NTOK)
                            + (ys & 7) * 8 + (xs & 7)) * CH;
#pragma unroll
        for (int k = 0; k < 6; k++) {
            int c = lane + k * 32;
            g_hw_bf[dst + c] = __float2bfloat16((t[c][j] - mean) * r * ln1w[c] + ln1b[c]);
        }
    }
}

// ---------------- mma.sync bf16 GEMM, CTA tile 128x192, 3-stage ----------------
// 512 threads = 16 warps (4m x 4n); warp tile 32x48 (2x6 m16n8k16 frags).
// MODE 0: qkv  -> g_qkv_bf HEAD-MAJOR layout
// MODE 1: proj -> g_xb2 = . + g_xb window-reverse
// MODE 2: fc1  -> GELU -> g_hid_bf
// MODE 3: fc2  -> out NCHW = clamp(. + g_xb2 + g_xb)
#define GSTAGE 40960
#define GSMEM  (3 * GSTAGE)   // 122880

template <int MODE>
__global__ void __launch_bounds__(512)
mma_gemm(const float* __restrict__ bias, float* __restrict__ outp) {
    constexpr int K    = (MODE == 3) ? HID : CH;
    constexpr int Nout = (MODE == 0) ? 3 * CH : (MODE == 2) ? HID : CH;
    constexpr int NST  = K / 64;
    const __nv_bfloat16* const A  = (MODE == 0) ? g_hw_bf : (MODE == 1) ? g_attn_bf
                                  : (MODE == 2) ? g_h2_bf : g_hid_bf;
    const __nv_bfloat16* const Bt = (MODE == 0) ? g_wqkv : (MODE == 1) ? g_wproj
                                  : (MODE == 2) ? g_wfc1 : g_wfc2;

    extern __shared__ __align__(1024) uint8_t smx[];
    const uint32_t smb = s2u(smx);
    const int tid = threadIdx.x;
    const int wid = tid >> 5, lane = tid & 31;
    const int wm = wid & 3, wn = wid >> 2;    // 4m x 4n
    const int m0 = blockIdx.y * 128;
    const int n0c = blockIdx.x * 192;

    const __nv_bfloat16* const Abase = A  + (size_t)m0 * K;
    const __nv_bfloat16* const Bbase = Bt + (size_t)n0c * K;

    auto load_stage = [&](int st) {
        const uint32_t sA = smb + (st % 3) * GSTAGE;
        const uint32_t sB = sA + 16384;
        const int kel = st * 64;
#pragma unroll
        for (int i = 0; i < 2; i++) {            // A: 128 rows x 128B
            int e = tid + i * 512;
            int row = e >> 3, c16 = e & 7;
            cp16(sA + sw128(row * 128 + c16 * 16), Abase + (size_t)row * K + kel + c16 * 8);
        }
#pragma unroll
        for (int i = 0; i < 3; i++) {            // B: 192 rows x 128B
            int e = tid + i * 512;
            int row = e >> 3, c16 = e & 7;
            cp16(sB + sw128(row * 128 + c16 * 16), Bbase + (size_t)row * K + kel + c16 * 8);
        }
    };

    float acc[2][6][4] = {};

    const int arow0 = wm * 32 + (lane & 15);
    const int akoff = (lane >> 4) * 16;
    const int brow0 = wn * 48 + (lane & 7) + ((lane >> 4) << 3);
    const int bkoff = (lane & 8) ? 16 : 0;

    load_stage(0); cp_commit();
    load_stage(1); cp_commit();
    load_stage(2); cp_commit();

    for (int st = 0; st < NST; st++) {
        cp_wait2();
        __syncthreads();
        const uint32_t sA = smb + (st % 3) * GSTAGE;
        const uint32_t sB = sA + 16384;
#pragma unroll
        for (int kk = 0; kk < 4; kk++) {
            uint32_t af[2][4], bf[3][4];
#pragma unroll
            for (int mi = 0; mi < 2; mi++)
                ldsm4(af[mi][0], af[mi][1], af[mi][2], af[mi][3],
                      sA + sw128((arow0 + mi * 16) * 128 + kk * 32 + akoff));
#pragma unroll
            for (int bi = 0; bi < 3; bi++)
                ldsm4(bf[bi][0], bf[bi][1], bf[bi][2], bf[bi][3],
                      sB + sw128((brow0 + bi * 16) * 128 + kk * 32 + bkoff));
#pragma unroll
            for (int mi = 0; mi < 2; mi++)
#pragma unroll
                for (int ni = 0; ni < 6; ni++)
                    mma16816(acc[mi][ni], af[mi], &bf[ni >> 1][(ni & 1) * 2]);
        }
        __syncthreads();
        if (st + 3 < NST) load_stage(st + 3);
        cp_commit();
    }

    // ---- epilogue ----
    const int g = lane >> 2, tg = lane & 3;
    const int nbase = n0c + wn * 48;
    float2 bv[6];
#pragma unroll
    for (int ni = 0; ni < 6; ni++) bv[ni] = *(const float2*)&bias[nbase + ni * 8 + tg * 2];

#pragma unroll
    for (int mi = 0; mi < 2; mi++) {
#pragma unroll
        for (int half = 0; half < 2; half++) {
            const int r = m0 + wm * 32 + mi * 16 + g + half * 8;
            if (MODE == 0) {
                // head-major: [win][head][mat][tok][32]
                const int win = r >> 6, tok = r & 63;
#pragma unroll
                for (int ni = 0; ni < 6; ni++) {
                    const int c = nbase + ni * 8 + tg * 2;
                    const int mat = c / 192, hc = c - mat * 192;
                    const int head = hc >> 5, dim = hc & 31;
                    float v0 = acc[mi][ni][half * 2 + 0] + bv[ni].x;
                    float v1 = acc[mi][ni][half * 2 + 1] + bv[ni].y;
                    __nv_bfloat162 h2 = __floats2bfloat162_rn(v0, v1);
                    *(__nv_bfloat162*)&g_qkv_bf[(((size_t)win * HEADS + head) * 3 + mat) * 2048
                                                + tok * 32 + dim] = h2;
                }
            } else if (MODE == 2) {
#pragma unroll
                for (int ni = 0; ni < 6; ni++) {
                    float v0 = acc[mi][ni][half * 2 + 0] + bv[ni].x;
                    float v1 = acc[mi][ni][half * 2 + 1] + bv[ni].y;
                    v0 = 0.5f * v0 * (1.f + erff(v0 * 0.7071067811865475f));
                    v1 = 0.5f * v1 * (1.f + erff(v1 * 0.7071067811865475f));
                    __nv_bfloat162 h2 = __floats2bfloat162_rn(v0, v1);
                    *(__nv_bfloat162*)&g_hid_bf[(size_t)r * Nout + nbase + ni * 8 + tg * 2] = h2;
                }
            } else if (MODE == 1) {
                const int win = r >> 6, tok = r & 63;
                const int bb2 = win >> 8, wy = (win >> 4) & 15, wx = win & 15;
                const int yy = ((wy << 3) + (tok >> 3) + SHIFT) & 127;
                const int xx = ((wx << 3) + (tok & 7) + SHIFT) & 127;
                const size_t dr = ((size_t)((bb2 * HH + yy) * WW + xx)) * CH;
#pragma unroll
                for (int ni = 0; ni < 6; ni++) {
                    const size_t o = dr + nbase + ni * 8 + tg * 2;
                    float2 sc = *(const float2*)&g_xb[o];
                    float2 ov;
                    ov.x = acc[mi][ni][half * 2 + 0] + bv[ni].x + sc.x;
                    ov.y = acc[mi][ni][half * 2 + 1] + bv[ni].y + sc.y;
                    *(float2*)&g_xb2[o] = ov;
                }
            } else {
                // MODE 3: direct NCHW clamped output
                const int bb2 = r >> 14, yy = (r >> 7) & 127, xx = r & 127;
                const size_t off = (size_t)r * CH;
                const size_t obase = (((size_t)bb2 * CH) * HH + yy) * WW + xx;
#pragma unroll
                for (int ni = 0; ni < 6; ni++) {
                    const size_t o = off + nbase + ni * 8 + tg * 2;
                    float2 a2 = *(const float2*)&g_xb2[o];
                    float2 a1 = *(const float2*)&g_xb[o];
                    float v0 = acc[mi][ni][half * 2 + 0] + bv[ni].x + a2.x + a1.x;
                    float v1 = acc[mi][ni][half * 2 + 1] + bv[ni].y + a2.y + a1.y;
                    v0 = fminf(10.f, fmaxf(-10.f, v0));
                    v1 = fminf(10.f, fmaxf(-10.f, v1));
                    const int c = nbase + ni * 8 + tg * 2;
                    outp[obase + (size_t)c * (HH * WW)] = v0;
                    outp[obase + (size_t)(c + 1) * (HH * WW)] = v1;
                }
            }
        }
    }
}

// ---------------- tensor-core windowed attention ----------------
// 1 block = 1 window; 12 warps = 6 heads x 2 row-halves (32 rows each).
#define ATT_SLICE 5120
#define ATT_QKV   (18 * ATT_SLICE)      // 92160
#define ATT_SMEM  (ATT_QKV + 5408)
__global__ void __launch_bounds__(384)
attn_kernel(const float* __restrict__ rpb) {
    extern __shared__ __align__(128) uint8_t smem_a[];
    float* srpb = (float*)(smem_a + ATT_QKV);
    const int win = blockIdx.x;
    const int tid = threadIdx.x;
    const int wid = tid >> 5, lane = tid & 31;
    const int head = wid >> 1, wrow = wid & 1;
    const int g = lane >> 2, tg = lane & 3;

    for (int f = tid; f < 225 * HEADS; f += 384) srpb[f] = rpb[f];

    {
        const __nv_bfloat16* gb = g_qkv_bf + (size_t)win * 18 * 2048;
#pragma unroll
        for (int i = 0; i < 12; i++) {
            int idx = tid + i * 384;
            int slice = idx >> 8;
            int cidx = idx & 255;
            int row = cidx >> 2, ch = cidx & 3;
            uint4 v = *(const uint4*)(gb + slice * 2048 + cidx * 8);
            *(uint4*)(smem_a + slice * ATT_SLICE + row * 80 + ch * 16) = v;
        }
    }
    __syncthreads();

    const uint32_t sq = s2u(smem_a) + (head * 3 + 0) * ATT_SLICE;
    const uint32_t sk = sq + ATT_SLICE;
    const uint32_t sv = sq + 2 * ATT_SLICE;

    // ---- QK^T ----
    float s[2][8][4] = {};
#pragma unroll
    for (int kt = 0; kt < 2; kt++) {
        uint32_t af[2][4];
#pragma unroll
        for (int mi = 0; mi < 2; mi++)
            ldsm4(af[mi][0], af[mi][1], af[mi][2], af[mi][3],
                  sq + (wrow * 32 + mi * 16 + (lane & 15)) * 80 + kt * 32 + (lane >> 4) * 16);
#pragma unroll
        for (int nj2 = 0; nj2 < 4; nj2++) {
            uint32_t bf[4];
            ldsm4(bf[0], bf[1], bf[2], bf[3],
                  sk + (nj2 * 16 + (lane & 7) + ((lane >> 4) << 3)) * 80
                     + kt * 32 + ((lane & 8) ? 16 : 0));
#pragma unroll
            for (int mi = 0; mi < 2; mi++) {
                mma16816(s[mi][nj2 * 2 + 0], af[mi], &bf[0]);
                mma16816(s[mi][nj2 * 2 + 1], af[mi], &bf[2]);
            }
        }
    }

    // ---- bias + mask + softmax ----
    const int wy = (win >> 4) & 15, wx = win & 15;
    const bool my = (wy == 15), mx = (wx == 15);
#pragma unroll
    for (int mi = 0; mi < 2; mi++)
#pragma unroll
        for (int nj = 0; nj < 8; nj++)
#pragma unroll
            for (int e = 0; e < 4; e++) {
                const int i = wrow * 32 + mi * 16 + g + ((e >= 2) ? 8 : 0);
                const int j = nj * 8 + tg * 2 + (e & 1);
                const int iy = i >> 3, ix = i & 7, jy = j >> 3, jx = j & 7;
                float v = s[mi][nj][e] * 0.17677669529663687f
                        + srpb[((iy - jy + 7) * 15 + (ix - jx + 7)) * HEADS + head];
                const int ri = (my ? (iy < 4 ? 1 : 2) : 0) * 3 + (mx ? (ix < 4 ? 1 : 2) : 0);
                const int rj = (my ? (jy < 4 ? 1 : 2) : 0) * 3 + (mx ? (jx < 4 ? 1 : 2) : 0);
                if (ri != rj) v -= 100.f;
                s[mi][nj][e] = v;
            }
#pragma unroll
    for (int mi = 0; mi < 2; mi++)
#pragma unroll
        for (int h = 0; h < 2; h++) {
            float m = -1e30f;
#pragma unroll
            for (int nj = 0; nj < 8; nj++) {
                m = fmaxf(m, s[mi][nj][h * 2 + 0]);
                m = fmaxf(m, s[mi][nj][h * 2 + 1]);
            }
            m = fmaxf(m, __shfl_xor_sync(0xffffffffu, m, 1));
            m = fmaxf(m, __shfl_xor_sync(0xffffffffu, m, 2));
            float sum = 0.f;
#pragma unroll
            for (int nj = 0; nj < 8; nj++) {
                float e0 = __expf(s[mi][nj][h * 2 + 0] - m);
                float e1 = __expf(s[mi][nj][h * 2 + 1] - m);
                s[mi][nj][h * 2 + 0] = e0;
                s[mi][nj][h * 2 + 1] = e1;
                sum += e0 + e1;
            }
            sum += __shfl_xor_sync(0xffffffffu, sum, 1);
            sum += __shfl_xor_sync(0xffffffffu, sum, 2);
            const float inv = 1.f / sum;
#pragma unroll
            for (int nj = 0; nj < 8; nj++) {
                s[mi][nj][h * 2 + 0] *= inv;
                s[mi][nj][h * 2 + 1] *= inv;
            }
        }

    // ---- P @ V ----
    float o[2][4][4] = {};
#pragma unroll
    for (int kt = 0; kt < 4; kt++) {
        const int jr = kt * 16 + (lane & 7) + ((lane & 8) ? 8 : 0);
        const uint32_t vb = sv + jr * 80 + (lane >> 4) * 16;
        uint32_t b0[4], b1[4];
        ldsm4t(b0[0], b0[1], b0[2], b0[3], vb);
        ldsm4t(b1[0], b1[1], b1[2], b1[3], vb + 32);
#pragma unroll
        for (int mi = 0; mi < 2; mi++) {
            uint32_t a[4];
            a[0] = packbf(s[mi][2 * kt][0], s[mi][2 * kt][1]);
            a[1] = packbf(s[mi][2 * kt][2], s[mi][2 * kt][3]);
            a[2] = packbf(s[mi][2 * kt + 1][0], s[mi][2 * kt + 1][1]);
            a[3] = packbf(s[mi][2 * kt + 1][2], s[mi][2 * kt + 1][3]);
            mma16816(o[mi][0], a, &b0[0]);
            mma16816(o[mi][1], a, &b0[2]);
            mma16816(o[mi][2], a, &b1[0]);
            mma16816(o[mi][3], a, &b1[2]);
        }
    }

    // ---- store O token-major [tok][192] ----
    __nv_bfloat16* ob = g_attn_bf + (size_t)(win * NTOK) * CH + head * HD;
#pragma unroll
    for (int mi = 0; mi < 2; mi++) {
        const int rlo = wrow * 32 + mi * 16 + g;
#pragma unroll
        for (int nf = 0; nf < 4; nf++) {
            const int d = nf * 8 + tg * 2;
            *(__nv_bfloat162*)&ob[(size_t)rlo * CH + d] =
                __floats2bfloat162_rn(o[mi][nf][0], o[mi][nf][1]);
            *(__nv_bfloat162*)&ob[(size_t)(rlo + 8) * CH + d] =
                __floats2bfloat162_rn(o[mi][nf][2], o[mi][nf][3]);
        }
    }
}

// ---------------- LN2 ----------------
__global__ void ln2_kernel(const float* __restrict__ w, const float* __restrict__ bias) {
    const int gw = (blockIdx.x * blockDim.x + threadIdx.x) >> 5;
    const int lane = threadIdx.x & 31;
    if (gw >= TOK) return;
    const float* row = g_xb2 + (size_t)gw * CH;
    float v[6];
    float s = 0.f, sq = 0.f;
#pragma unroll
    for (int k = 0; k < 6; k++) {
        v[k] = row[lane + k * 32];
        s += v[k]; sq += v[k] * v[k];
    }
#pragma unroll
    for (int o = 16; o; o >>= 1) {
        s  += __shfl_xor_sync(0xffffffffu, s, o);
        sq += __shfl_xor_sync(0xffffffffu, sq, o);
    }
    float mean = s * (1.f / CH);
    float var = sq * (1.f / CH) - mean * mean;
    float r = rsqrtf(var + 1e-5f);
    __nv_bfloat16* orow = g_h2_bf + (size_t)gw * CH;
#pragma unroll
    for (int k = 0; k < 6; k++) {
        int cc = lane + k * 32;
        orow[cc] = __float2bfloat16((v[k] - mean) * r * w[cc] + bias[cc]);
    }
}

// ---------------- launch ----------------
extern "C" void kernel_launch(void* const* d_in, const int* in_sizes, int n_in,
                              void* d_out, int out_size) {
    (void)in_sizes; (void)n_in; (void)out_size;
    const float* x      = (const float*)d_in[0];
    const float* gn_w   = (const float*)d_in[1];
    const float* gn_b   = (const float*)d_in[2];
    const float* ln1_w  = (const float*)d_in[3];
    const float* ln1_b  = (const float*)d_in[4];
    const float* qkv_w  = (const float*)d_in[5];
    const float* qkv_b  = (const float*)d_in[6];
    const float* proj_w = (const float*)d_in[7];
    const float* proj_b = (const float*)d_in[8];
    const float* rpb    = (const float*)d_in[9];
    const float* ln2_w  = (const float*)d_in[10];
    const float* ln2_b  = (const float*)d_in[11];
    const float* fc1_w  = (const float*)d_in[12];
    const float* fc1_b  = (const float*)d_in[13];
    const float* fc2_w  = (const float*)d_in[14];
    const float* fc2_b  = (const float*)d_in[15];
    float* out = (float*)d_out;

    cudaFuncSetAttribute((const void*)attn_kernel,
                         cudaFuncAttributeMaxDynamicSharedMemorySize, ATT_SMEM);
    cudaFuncSetAttribute((const void*)mma_gemm<0>, cudaFuncAttributeMaxDynamicSharedMemorySize, GSMEM);
    cudaFuncSetAttribute((const void*)mma_gemm<1>, cudaFuncAttributeMaxDynamicSharedMemorySize, GSMEM);
    cudaFuncSetAttribute((const void*)mma_gemm<2>, cudaFuncAttributeMaxDynamicSharedMemorySize, GSMEM);
    cudaFuncSetAttribute((const void*)mma_gemm<3>, cudaFuncAttributeMaxDynamicSharedMemorySize, GSMEM);

    wtrans_all<<<432, 256>>>(qkv_w, proj_w, fc1_w, fc2_w);

    gn_partial_kernel<<<BATCH * 128, 256>>>(x);
    gn_final_kernel<<<BATCH, 128>>>();
    build_kernel<<<BATCH * HH * (WW / 32), 256>>>(x, gn_w, gn_b, ln1_w, ln1_b);

    // QKV -> head-major g_qkv_bf
    mma_gemm<0><<<dim3(3, TOK / 128), 512, GSMEM>>>(qkv_b, nullptr);

    attn_kernel<<<NWIN, 384, ATT_SMEM>>>(rpb);

    // proj: window-reverse + shortcut -> g_xb2
    mma_gemm<1><<<dim3(1, TOK / 128), 512, GSMEM>>>(proj_b, nullptr);

    ln2_kernel<<<TOK / 8, 256>>>(ln2_w, ln2_b);

    // fc1 + GELU -> g_hid_bf
    mma_gemm<2><<<dim3(4, TOK / 128), 512, GSMEM>>>(fc1_b, nullptr);

    // fc2 + double residual + clamp -> out (NCHW)
    mma_gemm<3><<<dim3(1, TOK / 128), 512, GSMEM>>>(fc2_b, out);
}

// round 9
// speedup vs baseline: 1.0765x; 1.0765x over previous
#include <cuda_runtime.h>
#include <cuda_bf16.h>
#include <cstdint>
#include <math.h>

// Problem constants
#define BATCH 8
#define CH    192
#define HH    128
#define WW    128
#define HEADS 6
#define HD    32
#define WIN   8
#define NTOK  64
#define NWIN  2048
#define TOK   131072
#define HID   768
#define SHIFT 4

// ---------------- device scratch ----------------
__device__ __align__(256) float g_xb [TOK * CH];   // GN output NHWC fp32 (residual & shortcut)
__device__ __align__(256) float g_xb2[TOK * CH];   // xb + attn branch NHWC fp32
__device__ __align__(256) __nv_bfloat16 g_hw_bf [TOK * CH];
// qkv in head-major layout: [win][head][mat(q,k,v)][64 tok][32 dim]
__device__ __align__(256) __nv_bfloat16 g_qkv_bf[(size_t)TOK * 3 * CH];
__device__ __align__(256) __nv_bfloat16 g_attn_bf[TOK * CH];
__device__ __align__(256) __nv_bfloat16 g_h2_bf [TOK * CH];
__device__ __align__(256) __nv_bfloat16 g_hid_bf[(size_t)TOK * HID];
__device__ __align__(256) __nv_bfloat16 g_wqkv[3 * CH * CH];   // [576,192] (N,K)
__device__ __align__(256) __nv_bfloat16 g_wproj[CH * CH];      // [192,192]
__device__ __align__(256) __nv_bfloat16 g_wfc1[HID * CH];      // [768,192]
__device__ __align__(256) __nv_bfloat16 g_wfc2[CH * HID];      // [192,768]
__device__ float g_part[BATCH * 128 * 2];
__device__ float g_stats[BATCH * 2];

// ---------------- helpers ----------------
__device__ __forceinline__ uint32_t s2u(const void* p) {
    uint32_t a;
    asm("{ .reg .u64 t; cvta.to.shared.u64 t, %1; cvt.u32.u64 %0, t; }" : "=r"(a) : "l"(p));
    return a;
}
__device__ __forceinline__ uint32_t sw128(uint32_t o) { return o ^ ((o >> 3) & 0x70); }

__device__ __forceinline__ void cp16(uint32_t saddr, const void* gptr) {
    asm volatile("cp.async.cg.shared.global [%0], [%1], 16;" :: "r"(saddr), "l"(gptr) : "memory");
}
__device__ __forceinline__ void cp_commit() {
    asm volatile("cp.async.commit_group;" ::: "memory");
}
__device__ __forceinline__ void cp_wait1() {
    asm volatile("cp.async.wait_group 1;" ::: "memory");
}
__device__ __forceinline__ void ldsm4(uint32_t& r0, uint32_t& r1, uint32_t& r2, uint32_t& r3,
                                      uint32_t a) {
    asm volatile("ldmatrix.sync.aligned.m8n8.x4.shared.b16 {%0,%1,%2,%3}, [%4];"
                 : "=r"(r0), "=r"(r1), "=r"(r2), "=r"(r3) : "r"(a));
}
__device__ __forceinline__ void ldsm4t(uint32_t& r0, uint32_t& r1, uint32_t& r2, uint32_t& r3,
                                       uint32_t a) {
    asm volatile("ldmatrix.sync.aligned.m8n8.x4.trans.shared.b16 {%0,%1,%2,%3}, [%4];"
                 : "=r"(r0), "=r"(r1), "=r"(r2), "=r"(r3) : "r"(a));
}
__device__ __forceinline__ void mma16816(float* c, const uint32_t* a, const uint32_t* b) {
    asm volatile(
        "mma.sync.aligned.m16n8k16.row.col.f32.bf16.bf16.f32 "
        "{%0,%1,%2,%3}, {%4,%5,%6,%7}, {%8,%9}, {%0,%1,%2,%3};"
        : "+f"(c[0]), "+f"(c[1]), "+f"(c[2]), "+f"(c[3])
        : "r"(a[0]), "r"(a[1]), "r"(a[2]), "r"(a[3]), "r"(b[0]), "r"(b[1]));
}
__device__ __forceinline__ uint32_t packbf(float a, float b) {
    __nv_bfloat162 h = __floats2bfloat162_rn(a, b);
    return *(uint32_t*)&h;
}

// ---------------- GroupNorm two-stage reduction ----------------
__global__ void gn_partial_kernel(const float* __restrict__ x) {
    const int b = blockIdx.x >> 7;
    const int chunk = blockIdx.x & 127;
    const int tid = threadIdx.x;
    const size_t per_sample = (size_t)CH * HH * WW;
    const float* p = x + (size_t)b * per_sample + (size_t)chunk * 24576;
    float s = 0.f, sq = 0.f;
    for (int i = tid; i < 24576; i += 256) { float v = p[i]; s += v; sq += v * v; }
    __shared__ float rs[256], rq[256];
    rs[tid] = s; rq[tid] = sq;
    __syncthreads();
    for (int o = 128; o; o >>= 1) {
        if (tid < o) { rs[tid] += rs[tid + o]; rq[tid] += rq[tid + o]; }
        __syncthreads();
    }
    if (tid == 0) {
        g_part[blockIdx.x * 2 + 0] = rs[0];
        g_part[blockIdx.x * 2 + 1] = rq[0];
    }
}

__global__ void gn_final_kernel() {
    const int b = blockIdx.x;
    const int tid = threadIdx.x;
    __shared__ double ds[128], dq[128];
    ds[tid] = (double)g_part[(b * 128 + tid) * 2 + 0];
    dq[tid] = (double)g_part[(b * 128 + tid) * 2 + 1];
    __syncthreads();
    for (int o = 64; o; o >>= 1) {
        if (tid < o) { ds[tid] += ds[tid + o]; dq[tid] += dq[tid + o]; }
        __syncthreads();
    }
    if (tid == 0) {
        const double n = 3145728.0;
        double mean = ds[0] / n;
        double var = dq[0] / n - mean * mean;
        g_stats[b * 2 + 0] = (float)mean;
        g_stats[b * 2 + 1] = (float)(1.0 / sqrt(var + 1e-5));
    }
}

// ---------------- all weight transposes in one launch ----------------
__global__ void wtrans_all(const float* __restrict__ qkv_w, const float* __restrict__ proj_w,
                           const float* __restrict__ fc1_w, const float* __restrict__ fc2_w) {
    const int b = blockIdx.x;
    const float* W;
    __nv_bfloat16* Wt;
    int K, N, bx, by;
    if (b < 108)      { W = qkv_w;  Wt = g_wqkv;  K = CH;  N = 3 * CH; bx = b % 18;  by = b / 18; }
    else if (b < 144) { int t = b - 108; W = proj_w; Wt = g_wproj; K = CH;  N = CH;  bx = t % 6;  by = t / 6; }
    else if (b < 288) { int t = b - 144; W = fc1_w;  Wt = g_wfc1;  K = CH;  N = HID; bx = t % 24; by = t / 24; }
    else              { int t = b - 288; W = fc2_w;  Wt = g_wfc2;  K = HID; N = CH;  bx = t % 6;  by = t / 6; }
    __shared__ float t[32][33];
    const int k0 = by * 32, n0 = bx * 32;
    const int lx = threadIdx.x & 31, ly = threadIdx.x >> 5;
    for (int r = ly; r < 32; r += 8) t[r][lx] = W[(size_t)(k0 + r) * N + n0 + lx];
    __syncthreads();
    for (int r = ly; r < 32; r += 8)
        Wt[(size_t)(n0 + r) * K + k0 + lx] = __float2bfloat16(t[lx][r]);
}

// ---------------- GN apply + xb store + LN1 + shift + window partition ----------------
__global__ void build_kernel(const float* __restrict__ x,
                             const float* __restrict__ gnw, const float* __restrict__ gnb,
                             const float* __restrict__ ln1w, const float* __restrict__ ln1b) {
    __shared__ float t[CH][33];
    const int bid = blockIdx.x;
    const int xt = bid & 3;
    const int y  = (bid >> 2) & 127;
    const int b  = bid >> 9;
    const int tid = threadIdx.x;
    const float mu = g_stats[b * 2 + 0];
    const float rstd = g_stats[b * 2 + 1];
    const int lx = tid & 31;
    const int c0 = tid >> 5;

    for (int c = c0; c < CH; c += 8) {
        float v = x[((((size_t)b * CH + c) * HH + y) * WW) + xt * 32 + lx];
        t[c][lx] = (v - mu) * rstd * gnw[c] + gnb[c];
    }
    __syncthreads();

    const size_t tokbase = ((size_t)(b * HH + y) * WW) + xt * 32;
    for (int j = 0; j < 32; j++) {
        if (tid < CH) g_xb[(tokbase + j) * CH + tid] = t[tid][j];
    }

    const int warp = tid >> 5, lane = tid & 31;
    for (int j = warp; j < 32; j += 8) {
        float s = 0.f, sq = 0.f;
#pragma unroll
        for (int k = 0; k < 6; k++) {
            float v = t[lane + k * 32][j];
            s += v; sq += v * v;
        }
#pragma unroll
        for (int o = 16; o; o >>= 1) {
            s  += __shfl_xor_sync(0xffffffffu, s, o);
            sq += __shfl_xor_sync(0xffffffffu, sq, o);
        }
        float mean = s * (1.f / CH);
        float var = sq * (1.f / CH) - mean * mean;
        float r = rsqrtf(var + 1e-5f);
        const int xx = xt * 32 + j;
        const int ys = (y - SHIFT) & 127;
        const int xs = (xx - SHIFT) & 127;
        const size_t dst = ((size_t)(((b * 16 + (ys >> 3)) * 16 + (xs >> 3)) * NTOK)
                            + (ys & 7) * 8 + (xs & 7)) * CH;
#pragma unroll
        for (int k = 0; k < 6; k++) {
            int c = lane + k * 32;
            g_hw_bf[dst + c] = __float2bfloat16((t[c][j] - mean) * r * ln1w[c] + ln1b[c]);
        }
    }
}

// ---------------- mma.sync bf16 GEMM, CTA tile 128x96, 2-stage ----------------
// 256 threads = 8 warps (4m x 2n); warp tile 32x48 (2x6 m16n8k16 frags).
// MODE 0: qkv  -> g_qkv_bf HEAD-MAJOR layout
// MODE 1: proj -> g_xb2 = . + g_xb window-reverse
// MODE 2: fc1  -> GELU -> g_hid_bf
// MODE 3: fc2  -> out NCHW = clamp(. + g_xb2 + g_xb)
#define GSTAGE 28672
#define GSMEM  (2 * GSTAGE)   // 57344

template <int MODE>
__global__ void __launch_bounds__(256)
mma_gemm(const float* __restrict__ bias, float* __restrict__ outp) {
    constexpr int K    = (MODE == 3) ? HID : CH;
    constexpr int NST  = K / 64;
    const __nv_bfloat16* const A  = (MODE == 0) ? g_hw_bf : (MODE == 1) ? g_attn_bf
                                  : (MODE == 2) ? g_h2_bf : g_hid_bf;
    const __nv_bfloat16* const Bt = (MODE == 0) ? g_wqkv : (MODE == 1) ? g_wproj
                                  : (MODE == 2) ? g_wfc1 : g_wfc2;
    constexpr int Nout = (MODE == 0) ? 3 * CH : (MODE == 2) ? HID : CH;

    extern __shared__ __align__(1024) uint8_t smx[];
    const uint32_t smb = s2u(smx);
    const int tid = threadIdx.x;
    const int wid = tid >> 5, lane = tid & 31;
    const int wm = wid & 3, wn = wid >> 2;    // 4m x 2n
    const int m0 = blockIdx.y * 128;
    const int n0c = blockIdx.x * 96;

    const __nv_bfloat16* const Abase = A  + (size_t)m0 * K;
    const __nv_bfloat16* const Bbase = Bt + (size_t)n0c * K;

    auto load_stage = [&](int st, int buf) {
        const uint32_t sA = smb + buf * GSTAGE;
        const uint32_t sB = sA + 16384;
        const int kel = st * 64;
#pragma unroll
        for (int i = 0; i < 4; i++) {            // A: 128 rows x 128B
            int e = tid + i * 256;
            int row = e >> 3, c16 = e & 7;
            cp16(sA + sw128(row * 128 + c16 * 16), Abase + (size_t)row * K + kel + c16 * 8);
        }
#pragma unroll
        for (int i = 0; i < 3; i++) {            // B: 96 rows x 128B
            int e = tid + i * 256;
            int row = e >> 3, c16 = e & 7;
            cp16(sB + sw128(row * 128 + c16 * 16), Bbase + (size_t)row * K + kel + c16 * 8);
        }
    };

    float acc[2][6][4] = {};

    const int arow0 = wm * 32 + (lane & 15);
    const int akoff = (lane >> 4) * 16;
    const int brow0 = wn * 48 + (lane & 7) + ((lane >> 4) << 3);
    const int bkoff = (lane & 8) ? 16 : 0;

    load_stage(0, 0); cp_commit();
    load_stage(1, 1); cp_commit();

    for (int st = 0; st < NST; st++) {
        cp_wait1();
        __syncthreads();
        const int buf = st & 1;
        const uint32_t sA = smb + buf * GSTAGE;
        const uint32_t sB = sA + 16384;
#pragma unroll
        for (int kk = 0; kk < 4; kk++) {
            uint32_t af[2][4], bf[3][4];
#pragma unroll
            for (int mi = 0; mi < 2; mi++)
                ldsm4(af[mi][0], af[mi][1], af[mi][2], af[mi][3],
                      sA + sw128((arow0 + mi * 16) * 128 + kk * 32 + akoff));
#pragma unroll
            for (int bi = 0; bi < 3; bi++)
                ldsm4(bf[bi][0], bf[bi][1], bf[bi][2], bf[bi][3],
                      sB + sw128((brow0 + bi * 16) * 128 + kk * 32 + bkoff));
#pragma unroll
            for (int mi = 0; mi < 2; mi++)
#pragma unroll
                for (int ni = 0; ni < 6; ni++)
                    mma16816(acc[mi][ni], af[mi], &bf[ni >> 1][(ni & 1) * 2]);
        }
        __syncthreads();
        if (st + 2 < NST) load_stage(st + 2, buf);
        cp_commit();
    }

    // ---- epilogue ----
    const int g = lane >> 2, tg = lane & 3;
    const int nbase = n0c + wn * 48;
    float2 bv[6];
#pragma unroll
    for (int ni = 0; ni < 6; ni++) bv[ni] = *(const float2*)&bias[nbase + ni * 8 + tg * 2];

#pragma unroll
    for (int mi = 0; mi < 2; mi++) {
#pragma unroll
        for (int half = 0; half < 2; half++) {
            const int r = m0 + wm * 32 + mi * 16 + g + half * 8;
            if (MODE == 0) {
                // head-major: [win][head][mat][tok][32]
                const int win = r >> 6, tok = r & 63;
#pragma unroll
                for (int ni = 0; ni < 6; ni++) {
                    const int c = nbase + ni * 8 + tg * 2;
                    const int mat = c / 192, hc = c - mat * 192;
                    const int head = hc >> 5, dim = hc & 31;
                    float v0 = acc[mi][ni][half * 2 + 0] + bv[ni].x;
                    float v1 = acc[mi][ni][half * 2 + 1] + bv[ni].y;
                    __nv_bfloat162 h2 = __floats2bfloat162_rn(v0, v1);
                    *(__nv_bfloat162*)&g_qkv_bf[(((size_t)win * HEADS + head) * 3 + mat) * 2048
                                                + tok * 32 + dim] = h2;
                }
            } else if (MODE == 2) {
#pragma unroll
                for (int ni = 0; ni < 6; ni++) {
                    float v0 = acc[mi][ni][half * 2 + 0] + bv[ni].x;
                    float v1 = acc[mi][ni][half * 2 + 1] + bv[ni].y;
                    v0 = 0.5f * v0 * (1.f + erff(v0 * 0.7071067811865475f));
                    v1 = 0.5f * v1 * (1.f + erff(v1 * 0.7071067811865475f));
                    __nv_bfloat162 h2 = __floats2bfloat162_rn(v0, v1);
                    *(__nv_bfloat162*)&g_hid_bf[(size_t)r * Nout + nbase + ni * 8 + tg * 2] = h2;
                }
            } else if (MODE == 1) {
                const int win = r >> 6, tok = r & 63;
                const int bb2 = win >> 8, wy = (win >> 4) & 15, wx = win & 15;
                const int yy = ((wy << 3) + (tok >> 3) + SHIFT) & 127;
                const int xx = ((wx << 3) + (tok & 7) + SHIFT) & 127;
                const size_t dr = ((size_t)((bb2 * HH + yy) * WW + xx)) * CH;
#pragma unroll
                for (int ni = 0; ni < 6; ni++) {
                    const size_t o = dr + nbase + ni * 8 + tg * 2;
                    float2 sc = *(const float2*)&g_xb[o];
                    float2 ov;
                    ov.x = acc[mi][ni][half * 2 + 0] + bv[ni].x + sc.x;
                    ov.y = acc[mi][ni][half * 2 + 1] + bv[ni].y + sc.y;
                    *(float2*)&g_xb2[o] = ov;
                }
            } else {
                // MODE 3: direct NCHW clamped output
                const int bb2 = r >> 14, yy = (r >> 7) & 127, xx = r & 127;
                const size_t off = (size_t)r * CH;
                const size_t obase = (((size_t)bb2 * CH) * HH + yy) * WW + xx;
#pragma unroll
                for (int ni = 0; ni < 6; ni++) {
                    const size_t o = off + nbase + ni * 8 + tg * 2;
                    float2 a2 = *(const float2*)&g_xb2[o];
                    float2 a1 = *(const float2*)&g_xb[o];
                    float v0 = acc[mi][ni][half * 2 + 0] + bv[ni].x + a2.x + a1.x;
                    float v1 = acc[mi][ni][half * 2 + 1] + bv[ni].y + a2.y + a1.y;
                    v0 = fminf(10.f, fmaxf(-10.f, v0));
                    v1 = fminf(10.f, fmaxf(-10.f, v1));
                    const int c = nbase + ni * 8 + tg * 2;
                    outp[obase + (size_t)c * (HH * WW)] = v0;
                    outp[obase + (size_t)(c + 1) * (HH * WW)] = v1;
                }
            }
        }
    }
}

// ---------------- tensor-core windowed attention ----------------
// 1 block = 1 window; 12 warps = 6 heads x 2 row-halves (32 rows each).
#define ATT_SLICE 5120
#define ATT_QKV   (18 * ATT_SLICE)      // 92160
#define ATT_SMEM  (ATT_QKV + 5408)
__global__ void __launch_bounds__(384)
attn_kernel(const float* __restrict__ rpb) {
    extern __shared__ __align__(128) uint8_t smem_a[];
    float* srpb = (float*)(smem_a + ATT_QKV);
    const int win = blockIdx.x;
    const int tid = threadIdx.x;
    const int wid = tid >> 5, lane = tid & 31;
    const int head = wid >> 1, wrow = wid & 1;
    const int g = lane >> 2, tg = lane & 3;

    for (int f = tid; f < 225 * HEADS; f += 384) srpb[f] = rpb[f];

    {
        const __nv_bfloat16* gb = g_qkv_bf + (size_t)win * 18 * 2048;
#pragma unroll
        for (int i = 0; i < 12; i++) {
            int idx = tid + i * 384;
            int slice = idx >> 8;
            int cidx = idx & 255;
            int row = cidx >> 2, ch = cidx & 3;
            uint4 v = *(const uint4*)(gb + slice * 2048 + cidx * 8);
            *(uint4*)(smem_a + slice * ATT_SLICE + row * 80 + ch * 16) = v;
        }
    }
    __syncthreads();

    const uint32_t sq = s2u(smem_a) + (head * 3 + 0) * ATT_SLICE;
    const uint32_t sk = sq + ATT_SLICE;
    const uint32_t sv = sq + 2 * ATT_SLICE;

    // ---- QK^T ----
    float s[2][8][4] = {};
#pragma unroll
    for (int kt = 0; kt < 2; kt++) {
        uint32_t af[2][4];
#pragma unroll
        for (int mi = 0; mi < 2; mi++)
            ldsm4(af[mi][0], af[mi][1], af[mi][2], af[mi][3],
                  sq + (wrow * 32 + mi * 16 + (lane & 15)) * 80 + kt * 32 + (lane >> 4) * 16);
#pragma unroll
        for (int nj2 = 0; nj2 < 4; nj2++) {
            uint32_t bf[4];
            ldsm4(bf[0], bf[1], bf[2], bf[3],
                  sk + (nj2 * 16 + (lane & 7) + ((lane >> 4) << 3)) * 80
                     + kt * 32 + ((lane & 8) ? 16 : 0));
#pragma unroll
            for (int mi = 0; mi < 2; mi++) {
                mma16816(s[mi][nj2 * 2 + 0], af[mi], &bf[0]);
                mma16816(s[mi][nj2 * 2 + 1], af[mi], &bf[2]);
            }
        }
    }

    // ---- bias + mask + softmax ----
    const int wy = (win >> 4) & 15, wx = win & 15;
    const bool my = (wy == 15), mx = (wx == 15);
#pragma unroll
    for (int mi = 0; mi < 2; mi++)
#pragma unroll
        for (int nj = 0; nj < 8; nj++)
#pragma unroll
            for (int e = 0; e < 4; e++) {
                const int i = wrow * 32 + mi * 16 + g + ((e >= 2) ? 8 : 0);
                const int j = nj * 8 + tg * 2 + (e & 1);
                const int iy = i >> 3, ix = i & 7, jy = j >> 3, jx = j & 7;
                float v = s[mi][nj][e] * 0.17677669529663687f
                        + srpb[((iy - jy + 7) * 15 + (ix - jx + 7)) * HEADS + head];
                const int ri = (my ? (iy < 4 ? 1 : 2) : 0) * 3 + (mx ? (ix < 4 ? 1 : 2) : 0);
                const int rj = (my ? (jy < 4 ? 1 : 2) : 0) * 3 + (mx ? (jx < 4 ? 1 : 2) : 0);
                if (ri != rj) v -= 100.f;
                s[mi][nj][e] = v;
            }
#pragma unroll
    for (int mi = 0; mi < 2; mi++)
#pragma unroll
        for (int h = 0; h < 2; h++) {
            float m = -1e30f;
#pragma unroll
            for (int nj = 0; nj < 8; nj++) {
                m = fmaxf(m, s[mi][nj][h * 2 + 0]);
                m = fmaxf(m, s[mi][nj][h * 2 + 1]);
            }
            m = fmaxf(m, __shfl_xor_sync(0xffffffffu, m, 1));
            m = fmaxf(m, __shfl_xor_sync(0xffffffffu, m, 2));
            float sum = 0.f;
#pragma unroll
            for (int nj = 0; nj < 8; nj++) {
                float e0 = __expf(s[mi][nj][h * 2 + 0] - m);
                float e1 = __expf(s[mi][nj][h * 2 + 1] - m);
                s[mi][nj][h * 2 + 0] = e0;
                s[mi][nj][h * 2 + 1] = e1;
                sum += e0 + e1;
            }
            sum += __shfl_xor_sync(0xffffffffu, sum, 1);
            sum += __shfl_xor_sync(0xffffffffu, sum, 2);
            const float inv = 1.f / sum;
#pragma unroll
            for (int nj = 0; nj < 8; nj++) {
                s[mi][nj][h * 2 + 0] *= inv;
                s[mi][nj][h * 2 + 1] *= inv;
            }
        }

    // ---- P @ V ----
    float o[2][4][4] = {};
#pragma unroll
    for (int kt = 0; kt < 4; kt++) {
        const int jr = kt * 16 + (lane & 7) + ((lane & 8) ? 8 : 0);
        const uint32_t vb = sv + jr * 80 + (lane >> 4) * 16;
        uint32_t b0[4], b1[4];
        ldsm4t(b0[0], b0[1], b0[2], b0[3], vb);
        ldsm4t(b1[0], b1[1], b1[2], b1[3], vb + 32);
#pragma unroll
        for (int mi = 0; mi < 2; mi++) {
            uint32_t a[4];
            a[0] = packbf(s[mi][2 * kt][0], s[mi][2 * kt][1]);
            a[1] = packbf(s[mi][2 * kt][2], s[mi][2 * kt][3]);
            a[2] = packbf(s[mi][2 * kt + 1][0], s[mi][2 * kt + 1][1]);
            a[3] = packbf(s[mi][2 * kt + 1][2], s[mi][2 * kt + 1][3]);
            mma16816(o[mi][0], a, &b0[0]);
            mma16816(o[mi][1], a, &b0[2]);
            mma16816(o[mi][2], a, &b1[0]);
            mma16816(o[mi][3], a, &b1[2]);
        }
    }

    // ---- store O token-major [tok][192] ----
    __nv_bfloat16* ob = g_attn_bf + (size_t)(win * NTOK) * CH + head * HD;
#pragma unroll
    for (int mi = 0; mi < 2; mi++) {
        const int rlo = wrow * 32 + mi * 16 + g;
#pragma unroll
        for (int nf = 0; nf < 4; nf++) {
            const int d = nf * 8 + tg * 2;
            *(__nv_bfloat162*)&ob[(size_t)rlo * CH + d] =
                __floats2bfloat162_rn(o[mi][nf][0], o[mi][nf][1]);
            *(__nv_bfloat162*)&ob[(size_t)(rlo + 8) * CH + d] =
                __floats2bfloat162_rn(o[mi][nf][2], o[mi][nf][3]);
        }
    }
}

// ---------------- LN2 ----------------
__global__ void ln2_kernel(const float* __restrict__ w, const float* __restrict__ bias) {
    const int gw = (blockIdx.x * blockDim.x + threadIdx.x) >> 5;
    const int lane = threadIdx.x & 31;
    if (gw >= TOK) return;
    const float* row = g_xb2 + (size_t)gw * CH;
    float v[6];
    float s = 0.f, sq = 0.f;
#pragma unroll
    for (int k = 0; k < 6; k++) {
        v[k] = row[lane + k * 32];
        s += v[k]; sq += v[k] * v[k];
    }
#pragma unroll
    for (int o = 16; o; o >>= 1) {
        s  += __shfl_xor_sync(0xffffffffu, s, o);
        sq += __shfl_xor_sync(0xffffffffu, sq, o);
    }
    float mean = s * (1.f / CH);
    float var = sq * (1.f / CH) - mean * mean;
    float r = rsqrtf(var + 1e-5f);
    __nv_bfloat16* orow = g_h2_bf + (size_t)gw * CH;
#pragma unroll
    for (int k = 0; k < 6; k++) {
        int cc = lane + k * 32;
        orow[cc] = __float2bfloat16((v[k] - mean) * r * w[cc] + bias[cc]);
    }
}

// ---------------- launch ----------------
extern "C" void kernel_launch(void* const* d_in, const int* in_sizes, int n_in,
                              void* d_out, int out_size) {
    (void)in_sizes; (void)n_in; (void)out_size;
    const float* x      = (const float*)d_in[0];
    const float* gn_w   = (const float*)d_in[1];
    const float* gn_b   = (const float*)d_in[2];
    const float* ln1_w  = (const float*)d_in[3];
    const float* ln1_b  = (const float*)d_in[4];
    const float* qkv_w  = (const float*)d_in[5];
    const float* qkv_b  = (const float*)d_in[6];
    const float* proj_w = (const float*)d_in[7];
    const float* proj_b = (const float*)d_in[8];
    const float* rpb    = (const float*)d_in[9];
    const float* ln2_w  = (const float*)d_in[10];
    const float* ln2_b  = (const float*)d_in[11];
    const float* fc1_w  = (const float*)d_in[12];
    const float* fc1_b  = (const float*)d_in[13];
    const float* fc2_w  = (const float*)d_in[14];
    const float* fc2_b  = (const float*)d_in[15];
    float* out = (float*)d_out;

    cudaFuncSetAttribute((const void*)attn_kernel,
                         cudaFuncAttributeMaxDynamicSharedMemorySize, ATT_SMEM);
    cudaFuncSetAttribute((const void*)mma_gemm<0>, cudaFuncAttributeMaxDynamicSharedMemorySize, GSMEM);
    cudaFuncSetAttribute((const void*)mma_gemm<1>, cudaFuncAttributeMaxDynamicSharedMemorySize, GSMEM);
    cudaFuncSetAttribute((const void*)mma_gemm<2>, cudaFuncAttributeMaxDynamicSharedMemorySize, GSMEM);
    cudaFuncSetAttribute((const void*)mma_gemm<3>, cudaFuncAttributeMaxDynamicSharedMemorySize, GSMEM);

    wtrans_all<<<432, 256>>>(qkv_w, proj_w, fc1_w, fc2_w);

    gn_partial_kernel<<<BATCH * 128, 256>>>(x);
    gn_final_kernel<<<BATCH, 128>>>();
    build_kernel<<<BATCH * HH * (WW / 32), 256>>>(x, gn_w, gn_b, ln1_w, ln1_b);

    // QKV -> head-major g_qkv_bf
    mma_gemm<0><<<dim3(6, TOK / 128), 256, GSMEM>>>(qkv_b, nullptr);

    attn_kernel<<<NWIN, 384, ATT_SMEM>>>(rpb);

    // proj: window-reverse + shortcut -> g_xb2
    mma_gemm<1><<<dim3(2, TOK / 128), 256, GSMEM>>>(proj_b, nullptr);

    ln2_kernel<<<TOK / 8, 256>>>(ln2_w, ln2_b);

    // fc1 + GELU -> g_hid_bf
    mma_gemm<2><<<dim3(8, TOK / 128), 256, GSMEM>>>(fc1_b, nullptr);

    // fc2 + double residual + clamp -> out (NCHW)
    mma_gemm<3><<<dim3(2, TOK / 128), 256, GSMEM>>>(fc2_b, out);
}